// round 9
// baseline (speedup 1.0000x reference)
#include <cuda_runtime.h>

#define NN   4096
#define TT   300
#define TW   10
#define NBLK 128
#define NT1  256
#define NT2  512
#define CROWS 1536                            // smem-cached rows (slot words 0..47)
#define SMEM_CACHE (CROWS * 32 * 4)           // 196608 B: [row][32 floats]
#define SMEM_IDX   (16 * 392 * 2)             // 12544 B:  u16 idx[16][392]
#define SMEM_PART  (16 * 8 * 16)              // 2048 B:   float4 part[16][8]
#define SMEM_SZ    (SMEM_CACHE + SMEM_IDX + SMEM_PART)

// ---------------- device scratch ----------------
__device__ unsigned g_mask[NN * TW];
__device__ float    g_Xpart[4ull * 320 * NN];
__device__ __align__(256) unsigned long long g_slot[TT][NBLK];   // {tag=t+1, mask}

__device__ __forceinline__ unsigned long long ldcg64(const unsigned long long* p) {
    unsigned long long v; asm volatile("ld.global.cg.b64 %0, [%1];" : "=l"(v) : "l"(p)); return v;
}
__device__ __forceinline__ void stcg64(unsigned long long* p, unsigned long long v) {
    asm volatile("st.global.cg.b64 [%0], %1;" :: "l"(p), "l"(v));
}
__device__ __forceinline__ float4 ldcg128(const float* p) {
    float4 v;
    asm volatile("ld.global.cg.v4.f32 {%0,%1,%2,%3}, [%4];"
                 : "=f"(v.x), "=f"(v.y), "=f"(v.z), "=f"(v.w) : "l"(p));
    return v;
}

// ---------------- kernel 1: pack inp bits + clear slot tags ----------------
__global__ void __launch_bounds__(256) pack_kernel(const int* __restrict__ inp) {
    const int blk  = blockIdx.x;
    const int word = blk % TW;
    const int i    = (blk / TW) * 256 + threadIdx.x;
    unsigned m = 0u;
    const int tb = word * 32;
    #pragma unroll
    for (int b = 0; b < 32; ++b) {
        int t = tb + b;
        if (t < TT) m |= (((unsigned)inp[(size_t)t * NN + i]) & 1u) << b;
    }
    g_mask[i * TW + word] = m;
    int gid = blk * 256 + threadIdx.x;
    if (gid < TT * NBLK) ((unsigned long long*)g_slot)[gid] = 0ull;
}

// ---------------- kernel 2: X partials via packed f32x2 FFMA (exact) ----------
__global__ void __launch_bounds__(NT1) xgemm_kernel(const float* __restrict__ w) {
    __shared__ unsigned long long Adup[128][18];
    const int tid  = threadIdx.x;
    const int tile = blockIdx.x;
    int word = tile % 10;
    int ccq  = tile / 10;
    int cc   = ccq >> 2;
    int q    = ccq & 3;
    int j    = cc * 256 + tid;
    int ibase = q * 1024;

    unsigned long long acc[16];
    #pragma unroll
    for (int k = 0; k < 16; ++k) acc[k] = 0ull;

    for (int sub = 0; sub < 8; ++sub) {
        int ib = ibase + sub * 128;
        __syncthreads();
        for (int e = tid; e < 2048; e += NT1) {
            int ii = e >> 4, tp = e & 15;
            unsigned m  = g_mask[(ib + ii) * TW + word];
            unsigned lo = (m >> (2 * tp))     & 1u ? 0x3f800000u : 0u;
            unsigned hi = (m >> (2 * tp + 1)) & 1u ? 0x3f800000u : 0u;
            Adup[ii][tp] = ((unsigned long long)hi << 32) | lo;
        }
        __syncthreads();
        for (int ii = 0; ii < 128; ++ii) {
            unsigned wu = __float_as_uint(w[(size_t)(ib + ii) * NN + j]);
            unsigned long long wpk;
            asm("mov.b64 %0, {%1, %1};" : "=l"(wpk) : "r"(wu));
            const ulonglong2* ap = (const ulonglong2*)(&Adup[ii][0]);
            #pragma unroll
            for (int k = 0; k < 8; ++k) {
                ulonglong2 a2 = ap[k];
                asm("fma.rn.f32x2 %0, %1, %2, %0;" : "+l"(acc[2*k])   : "l"(wpk), "l"(a2.x));
                asm("fma.rn.f32x2 %0, %1, %2, %0;" : "+l"(acc[2*k+1]) : "l"(wpk), "l"(a2.y));
            }
        }
    }
    #pragma unroll
    for (int tp = 0; tp < 16; ++tp) {
        int t0 = word * 32 + 2 * tp;
        g_Xpart[((size_t)q * 320 + t0)     * NN + j] = __uint_as_float((unsigned)acc[tp]);
        g_Xpart[((size_t)q * 320 + t0 + 1) * NN + j] = __uint_as_float((unsigned)(acc[tp] >> 32));
    }
}

// ---------------- kernel 3: persistent recurrent LIF --------------------------
// 16 warps/block: warps 0-3 own cached words 0-47 (12 each, smem gather);
// warps 4-11 own 7 uncached words each, warps 12-15 own 6 (L2 gather).
// Each warp polls ITS OWN slot words; one __syncthreads per step.
__global__ void __launch_bounds__(NT2, 1)
lif_kernel(const float* __restrict__ w_rec, float* __restrict__ out) {
    extern __shared__ char sm[];
    float* cache = (float*)sm;                                           // [CROWS][32]
    unsigned short (*sh_idx)[392] = (unsigned short(*)[392])(sm + SMEM_CACHE);
    float4 (*part4)[8] = (float4(*)[8])(sm + SMEM_CACHE + SMEM_IDX);

    const int tid = threadIdx.x;
    const int bid = blockIdx.x;
    const int l   = tid & 31;
    const int wp  = tid >> 5;
    const int sub = l >> 3;        // row within 4-row wave
    const int ln8 = l & 7;         // 16B chunk within 128B segment
    const int j0  = bid * 32;

    // per-warp slot-word ownership
    const int wcnt   = (wp < 4) ? 12 : ((wp < 12) ? 7 : 6);
    const int wstart = (wp < 4) ? 12 * wp
                                : ((wp < 12) ? 48 + 7 * (wp - 4)
                                             : 104 + 6 * (wp - 12));

    // ---- preload smem weight cache: rows 0..CROWS-1, this block's 32 columns ----
    for (int q = tid; q < CROWS * 8; q += NT2) {
        int row = q >> 3, c8 = q & 7;
        ((float4*)cache)[q] = ldcg128(w_rec + (size_t)row * NN + j0 + c8 * 4);
    }
    __syncthreads();

    float v = 0.f, rt = 0.f, tl = 1.f;
    const float DECAY = 0.99004983374916805f;   // fp32(exp(-1/100))

    for (int t = 0; t < TT; ++t) {
        float x0 = 0.f, x1 = 0.f, x2 = 0.f, x3 = 0.f;
        if (wp == 0) {
            const int j = j0 + l;
            x0 = g_Xpart[(size_t)(0 * 320 + t) * NN + j];
            x1 = g_Xpart[(size_t)(1 * 320 + t) * NN + j];
            x2 = g_Xpart[(size_t)(2 * 320 + t) * NN + j];
            x3 = g_Xpart[(size_t)(3 * 320 + t) * NN + j];
        }

        int cnt = 0;
        if (t > 0) {
            // ---- distributed poll: lane k < wcnt polls slot word wstart+k ----
            const unsigned long long* slot = &g_slot[t - 1][wstart];
            const unsigned want = (unsigned)t;
            unsigned long long u = 0ull;
            bool ok = (l >= wcnt);
            while (1) {
                if (!ok) {
                    u = ldcg64(slot + l);
                    ok = ((unsigned)(u >> 32) == want);
                }
                if (__all_sync(0xffffffffu, ok)) break;
                if (!ok) __nanosleep(64);       // keep poll rate under LTS service
            }
            unsigned mymask = (unsigned)u;      // lanes >= wcnt hold 0
            // ---- in-warp parallel expansion via fns ----
            #pragma unroll
            for (int k = 0; k < 12; ++k) {
                if (k >= wcnt) break;
                unsigned m = __shfl_sync(0xffffffffu, mymask, k);
                int c = __popc(m);
                if (l < c)
                    sh_idx[wp][cnt + l] =
                        (unsigned short)(((wstart + k) << 5) + __fns(m, 0, l + 1));
                cnt += c;
            }
            __syncwarp();
        }

        // ---- gather (4 rows per wave, batch of 8 waves in flight) ----
        float4 acc = make_float4(0.f, 0.f, 0.f, 0.f);
        if (wp < 4) {
            for (int base = 0; base < cnt; base += 32) {
                float4 rv[8];
                #pragma unroll
                for (int u8 = 0; u8 < 8; ++u8) {
                    int kk = base + 4 * u8 + sub;
                    float4 z = make_float4(0.f, 0.f, 0.f, 0.f);
                    if (kk < cnt) {
                        int row = sh_idx[wp][kk];
                        z = *(const float4*)(cache + row * 32 + ln8 * 4);
                    }
                    rv[u8] = z;
                }
                #pragma unroll
                for (int u8 = 0; u8 < 8; ++u8) {
                    acc.x += rv[u8].x; acc.y += rv[u8].y;
                    acc.z += rv[u8].z; acc.w += rv[u8].w;
                }
            }
        } else {
            const float* wr = w_rec + j0 + (ln8 << 2);
            for (int base = 0; base < cnt; base += 32) {
                float4 rv[8];
                #pragma unroll
                for (int u8 = 0; u8 < 8; ++u8) {
                    int kk = base + 4 * u8 + sub;
                    float4 z = make_float4(0.f, 0.f, 0.f, 0.f);
                    if (kk < cnt) {
                        size_t row = sh_idx[wp][kk];
                        z = ldcg128(wr + (row << 12));
                    }
                    rv[u8] = z;
                }
                #pragma unroll
                for (int u8 = 0; u8 < 8; ++u8) {
                    acc.x += rv[u8].x; acc.y += rv[u8].y;
                    acc.z += rv[u8].z; acc.w += rv[u8].w;
                }
            }
        }
        // reduce the 4 sub-rows within the warp
        acc.x += __shfl_down_sync(0xffffffffu, acc.x, 16);
        acc.y += __shfl_down_sync(0xffffffffu, acc.y, 16);
        acc.z += __shfl_down_sync(0xffffffffu, acc.z, 16);
        acc.w += __shfl_down_sync(0xffffffffu, acc.w, 16);
        acc.x += __shfl_down_sync(0xffffffffu, acc.x, 8);
        acc.y += __shfl_down_sync(0xffffffffu, acc.y, 8);
        acc.z += __shfl_down_sync(0xffffffffu, acc.z, 8);
        acc.w += __shfl_down_sync(0xffffffffu, acc.w, 8);
        if (l < 8) part4[wp][ln8] = acc;
        __syncthreads();   // the ONLY per-step block barrier

        if (wp == 0) {
            const float* pf = (const float*)part4;   // [16][32 floats]
            float xr = 0.f;
            #pragma unroll
            for (int w16 = 0; w16 < 16; ++w16) xr += pf[w16 * 32 + l];
            float xt = xr + ((x0 + x1) + (x2 + x3));
            // LIF dynamics, exact reference order
            v *= DECAY;
            float xin = (rt > 0.f) ? 0.f : xt;
            rt -= 1.f;
            v += xin;
            bool sp = (v >= 10.f);
            if (sp) { tl = (float)t / 300.0f; rt = 1.f; v = 0.f; }

            unsigned ball = __ballot_sync(0xffffffffu, sp);
            if (t < TT - 1 && l == 0)
                stcg64(&g_slot[t][bid],
                       ((unsigned long long)(unsigned)(t + 1) << 32) |
                       (unsigned long long)ball);
            const int j = j0 + l;
            out[(size_t)t * NN + j]            = sp ? 1.f : 0.f;
            out[(size_t)(TT + t) * NN + j]     = tl;
            out[(size_t)(2 * TT + t) * NN + j] = v;
        }
        // WAR safety without a second barrier: any warp's poll(t+1) succeeds only
        // after ALL blocks publish step t, and each block's publish happens after
        // its warp 0 has consumed part4(t). sh_idx is warp-private.
    }
}

// ---------------- launch ----------------
extern "C" void kernel_launch(void* const* d_in, const int* in_sizes, int n_in,
                              void* d_out, int out_size) {
    const int* inp; const float* w; const float* w_rec;
    if (in_sizes[0] == TT * NN) {
        inp = (const int*)d_in[0]; w = (const float*)d_in[1]; w_rec = (const float*)d_in[2];
    } else if (n_in > 1 && in_sizes[1] == TT * NN) {
        inp = (const int*)d_in[1]; w = (const float*)d_in[0]; w_rec = (const float*)d_in[2];
    } else {
        inp = (const int*)d_in[2]; w = (const float*)d_in[0]; w_rec = (const float*)d_in[1];
    }
    float* out = (float*)d_out;

    cudaFuncSetAttribute(lif_kernel, cudaFuncAttributeMaxDynamicSharedMemorySize, SMEM_SZ);

    pack_kernel<<<160, 256>>>(inp);
    xgemm_kernel<<<640, NT1>>>(w);
    lif_kernel<<<NBLK, NT2, SMEM_SZ>>>(w_rec, out);
}